// round 7
// baseline (speedup 1.0000x reference)
#include <cuda_runtime.h>
#include <math.h>

#define Bx  8
#define Hx  128
#define Lx  8192
#define Nx  32
#define NCx 16
#define Tx  512
#define XSTR 516  // padded smem row stride for x staging (bank-spread)

// ---------------- device scratch (no allocations allowed) ----------------
__device__ float2 g_w [Hx*Nx];
__device__ float2 g_wT[Hx*Nx];
__device__ float2 g_K0[Hx*Nx];
__device__ float2 g_K1[Hx*Nx];

__device__ float2 g_U  [Bx*Hx*NCx*Nx];
__device__ float2 g_Lb [Bx*Hx*NCx*Nx];
__device__ float2 g_Sin[Bx*Hx*NCx*Nx];
__device__ float2 g_Rin[Bx*Hx*NCx*Nx];

__device__ float g_yf[Bx*Hx*Lx];
__device__ float g_yb[Bx*Hx*Lx];
__device__ float g_g [Bx*Hx*Lx];
__device__ float g_z [Bx*Hx*Lx];

__device__ float2 g_part[Hx*16];
__device__ float  g_scale[Hx];
__device__ float  g_shift[Hx];

// ---------------- setup: discretized SSM parameters ----------------
__global__ void k_setup(const float* __restrict__ C_re, const float* __restrict__ C_im,
                        const float* __restrict__ lAr,  const float* __restrict__ Aim,
                        const float* __restrict__ ldt) {
    int i = blockIdx.x * blockDim.x + threadIdx.x;
    if (i >= Hx * Nx) return;
    int h = i / Nx;
    float ar = expf(lAr[i]);
    float ai = Aim[i];
    float dt = expf(ldt[h]);
    // w = exp(dt*A), A = -ar + i*ai
    float mag = expf(-dt * ar);
    float sn, cs;
    sincosf(dt * ai, &sn, &cs);
    float wre = mag * cs, wim = mag * sn;
    g_w[i] = make_float2(wre, wim);
    // w^T in double (phase can be thousands of radians)
    double magT = exp(-(double)dt * (double)ar * (double)Tx);
    double phT  = (double)dt * (double)ai * (double)Tx;
    g_wT[i] = make_float2((float)(magT * cos(phT)), (float)(magT * sin(phT)));
    // F = (w-1)/A = (w-1)*conj(A)/|A|^2
    float den = ar * ar + ai * ai;
    float nre = (wre - 1.0f) * (-ar) + wim * ai;
    float nim = wim * (-ar) - (wre - 1.0f) * ai;
    float Fre = nre / den, Fim = nim / den;
    float c0r = C_re[i], c0i = C_im[i];
    g_K0[i] = make_float2(2.0f * (c0r * Fre - c0i * Fim), 2.0f * (c0r * Fim + c0i * Fre));
    float c1r = C_re[Hx * Nx + i], c1i = C_im[Hx * Nx + i];
    g_K1[i] = make_float2(2.0f * (c1r * Fre - c1i * Fim), 2.0f * (c1r * Fim + c1i * Fre));
}

// ---------------- pass 1: per-chunk local states (no outputs) ----------------
// warp w of each block handles chunk index widx = blockIdx.x*8 + w,
// widx = ((b*Hx+h)*NCx + c); lanes = 32 modes.
__global__ void k_pass1(const float* __restrict__ x) {
    __shared__ float xs[8 * Tx];
    int widx0 = blockIdx.x * 8;
    int base = widx0 * Tx;                 // contiguous (NCx*Tx == Lx, 8 | NCx)
    for (int i = threadIdx.x; i < 8 * Tx; i += blockDim.x) xs[i] = x[base + i];
    __syncthreads();

    int w = threadIdx.x >> 5, lane = threadIdx.x & 31;
    int widx = widx0 + w;
    int h = (widx / NCx) % Hx;
    float2 wv = g_w[h * Nx + lane];
    const float* xp = xs + w * Tx;

    float ur = 0.f, ui = 0.f;
#pragma unroll 8
    for (int t = 0; t < Tx; t++) {
        float xv = xp[t];
        float nr = fmaf(wv.x, ur, fmaf(-wv.y, ui, xv));
        float ni = fmaf(wv.x, ui, wv.y * ur);
        ur = nr; ui = ni;
    }
    g_U[widx * Nx + lane] = make_float2(ur, ui);

    float lr = 0.f, li = 0.f;
#pragma unroll 8
    for (int t = Tx - 1; t >= 0; t--) {
        float xv = xp[t];
        float nr = fmaf(wv.x, lr, fmaf(-wv.y, li, xv));
        float ni = fmaf(wv.x, li, wv.y * lr);
        lr = nr; li = ni;
    }
    g_Lb[widx * Nx + lane] = make_float2(lr, li);
}

// ---------------- combine carries across chunks ----------------
__global__ void k_carry() {
    int tau = blockIdx.x * blockDim.x + threadIdx.x;   // B*H*N = 32768 threads
    int bh = tau >> 5, n = tau & 31;
    int h = bh % Hx;
    float2 wT = g_wT[h * Nx + n];
    int base = bh * NCx * Nx + n;

    float sr = 0.f, si = 0.f;
    for (int c = 0; c < NCx; c++) {
        int idx = base + c * Nx;
        g_Sin[idx] = make_float2(sr, si);
        float2 u = g_U[idx];
        float nr = fmaf(wT.x, sr, fmaf(-wT.y, si, u.x));
        float ni = fmaf(wT.x, si, fmaf(wT.y, sr, u.y));
        sr = nr; si = ni;
    }
    float rr = 0.f, ri = 0.f;
    for (int c = NCx - 1; c >= 0; c--) {
        int idx = base + c * Nx;
        g_Rin[idx] = make_float2(rr, ri);
        float2 lb = g_Lb[idx];
        float nr = fmaf(wT.x, rr, fmaf(-wT.y, ri, lb.x));
        float ni = fmaf(wT.x, ri, fmaf(wT.y, rr, lb.y));
        rr = nr; ri = ni;
    }
}

// ---------------- pass 2: emit outputs ----------------
// block = (h, chunk c), 64 threads = 2 warps (fwd / bwd).
// lane = b*4 + q, q indexes an 8-mode group; 2 shuffles per step, 8 outputs per warp-step.
__global__ void k_pass2(const float* __restrict__ x) {
    __shared__ float xs[Bx * XSTR];
    int h = blockIdx.x / NCx, c = blockIdx.x % NCx;
    for (int i = threadIdx.x; i < Bx * Tx; i += blockDim.x) {
        int b = i >> 9, t = i & (Tx - 1);
        xs[b * XSTR + t] = x[((b * Hx + h) << 13) + (c << 9) + t];
    }
    __syncthreads();

    int warp = threadIdx.x >> 5;   // 0 = fwd, 1 = bwd
    int lane = threadIdx.x & 31;
    int b = lane >> 2, q = lane & 3;

    float wr[8], wi[8], kr[8], ki[8], sr[8], si[8];
    int pbase = h * Nx + q * 8;
    int sbase = ((b * Hx + h) * NCx + c) * Nx + q * 8;
#pragma unroll
    for (int m = 0; m < 8; m++) {
        float2 wv = g_w[pbase + m];  wr[m] = wv.x; wi[m] = wv.y;
        float2 kv = warp ? g_K1[pbase + m] : g_K0[pbase + m];
        kr[m] = kv.x; ki[m] = kv.y;
        float2 sv = warp ? g_Rin[sbase + m] : g_Sin[sbase + m];
        sr[m] = sv.x; si[m] = sv.y;
    }

    int obase = ((b * Hx + h) << 13) + (c << 9);
    const float* xp = xs + b * XSTR;

    if (warp == 0) {
#pragma unroll 2
        for (int t = 0; t < Tx; t++) {
            float xv = xp[t];
            float v = 0.f;
#pragma unroll
            for (int m = 0; m < 8; m++) {
                float nr = fmaf(wr[m], sr[m], fmaf(-wi[m], si[m], xv));
                float ni = fmaf(wr[m], si[m], wi[m] * sr[m]);
                sr[m] = nr; si[m] = ni;
                v = fmaf(kr[m], nr, fmaf(-ki[m], ni, v));
            }
            v += __shfl_xor_sync(0xffffffffu, v, 1);
            v += __shfl_xor_sync(0xffffffffu, v, 2);
            if (q == 0) g_yf[obase + t] = v;
        }
    } else {
#pragma unroll 2
        for (int t = Tx - 1; t >= 0; t--) {
            float xv = xp[t];
            float v = 0.f;
#pragma unroll
            for (int m = 0; m < 8; m++)
                v = fmaf(kr[m], sr[m], fmaf(-ki[m], si[m], v));
            v += __shfl_xor_sync(0xffffffffu, v, 1);
            v += __shfl_xor_sync(0xffffffffu, v, 2);
            if (q == 0) g_yb[obase + t] = v;
#pragma unroll
            for (int m = 0; m < 8; m++) {
                float nr = fmaf(wr[m], sr[m], fmaf(-wi[m], si[m], xv));
                float ni = fmaf(wr[m], si[m], wi[m] * sr[m]);
                sr[m] = nr; si[m] = ni;
            }
        }
    }
}

// ---------------- g = gelu(yf + yb + D*x) ----------------
__global__ void k_act(const float* __restrict__ x, const float* __restrict__ D) {
    int i4 = blockIdx.x * blockDim.x + threadIdx.x;     // 2,097,152 float4s
    int flat = i4 << 2;
    int ch = (flat >> 13) & (Hx - 1);
    float dv = __ldg(&D[ch]);
    float4 f  = ((const float4*)g_yf)[i4];
    float4 bb = ((const float4*)g_yb)[i4];
    float4 xv = ((const float4*)x)[i4];
    float u0 = f.x + bb.x + dv * xv.x;
    float u1 = f.y + bb.y + dv * xv.y;
    float u2 = f.z + bb.z + dv * xv.z;
    float u3 = f.w + bb.w + dv * xv.w;
    const float is2 = 0.70710678118654752f;
    float4 r;
    r.x = 0.5f * u0 * (1.0f + erff(u0 * is2));
    r.y = 0.5f * u1 * (1.0f + erff(u1 * is2));
    r.z = 0.5f * u2 * (1.0f + erff(u2 * is2));
    r.w = 0.5f * u3 * (1.0f + erff(u3 * is2));
    ((float4*)g_g)[i4] = r;
}

// ---------------- pointwise conv: z[b,o,l] = sum_h W[o,h]*g[b,h,l] ----------------
__global__ void k_gemm(const float* __restrict__ W) {
    __shared__ float Ws[64][68];
    __shared__ float gs[64][68];
    int l0 = blockIdx.x * 64;
    int o0 = blockIdx.y * 64;
    int b  = blockIdx.z;
    int tx = threadIdx.x & 15, ty = threadIdx.x >> 4;
    float acc[4][4] = {};

    for (int hc = 0; hc < Hx; hc += 64) {
        __syncthreads();
        for (int r = threadIdx.x; r < 4096; r += 256) {
            int oo = r >> 6, hh = r & 63;
            Ws[hh][oo] = W[(o0 + oo) * Hx + hc + hh];
        }
        for (int r = threadIdx.x; r < 4096; r += 256) {
            int hh = r >> 6, ll = r & 63;
            gs[hh][ll] = g_g[((b * Hx + hc + hh) << 13) + l0 + ll];
        }
        __syncthreads();
#pragma unroll 8
        for (int hh = 0; hh < 64; hh++) {
            float4 wv = *(const float4*)&Ws[hh][ty * 4];
            float4 gv = *(const float4*)&gs[hh][tx * 4];
            float wa[4] = {wv.x, wv.y, wv.z, wv.w};
            float ga[4] = {gv.x, gv.y, gv.z, gv.w};
#pragma unroll
            for (int i = 0; i < 4; i++)
#pragma unroll
                for (int j = 0; j < 4; j++)
                    acc[i][j] = fmaf(wa[i], ga[j], acc[i][j]);
        }
    }
#pragma unroll
    for (int i = 0; i < 4; i++) {
        int row = ((b * Hx + o0 + ty * 4 + i) << 13) + l0 + tx * 4;
        *(float4*)&g_z[row] = make_float4(acc[i][0], acc[i][1], acc[i][2], acc[i][3]);
    }
}

// ---------------- BN statistics (deterministic two-level reduction) ----------------
__global__ void k_bnstat() {
    int ch = blockIdx.x, seg = blockIdx.y;
    float s = 0.f, s2 = 0.f;
    for (int j = 0; j < 16; j++) {
        int f = seg * 4096 + j * 256 + threadIdx.x;
        int b = f >> 13, l = f & (Lx - 1);
        float v = g_z[((b * Hx + ch) << 13) + l];
        s += v;
        s2 = fmaf(v, v, s2);
    }
    __shared__ float rs[256], rq[256];
    rs[threadIdx.x] = s; rq[threadIdx.x] = s2;
    __syncthreads();
    for (int st = 128; st > 0; st >>= 1) {
        if (threadIdx.x < st) {
            rs[threadIdx.x] += rs[threadIdx.x + st];
            rq[threadIdx.x] += rq[threadIdx.x + st];
        }
        __syncthreads();
    }
    if (threadIdx.x == 0) g_part[ch * 16 + seg] = make_float2(rs[0], rq[0]);
}

__global__ void k_bnfin(const float* __restrict__ gamma, const float* __restrict__ beta) {
    int ch = threadIdx.x;
    double s = 0.0, s2 = 0.0;
    for (int j = 0; j < 16; j++) {
        float2 p = g_part[ch * 16 + j];
        s += p.x; s2 += p.y;
    }
    double cnt = (double)Bx * (double)Lx;
    double mean = s / cnt;
    double var = s2 / cnt - mean * mean;
    float scale = (float)((double)gamma[ch] / sqrt(var + 1e-5));
    g_scale[ch] = scale;
    g_shift[ch] = beta[ch] - (float)mean * scale;
}

// ---------------- out = elu(bn(z)) + x ----------------
__global__ void k_final(const float* __restrict__ x, float* __restrict__ out) {
    int i4 = blockIdx.x * blockDim.x + threadIdx.x;
    int flat = i4 << 2;
    int ch = (flat >> 13) & (Hx - 1);
    float sc = __ldg(&g_scale[ch]);
    float sh = __ldg(&g_shift[ch]);
    float4 z  = ((const float4*)g_z)[i4];
    float4 xv = ((const float4*)x)[i4];
    float u0 = fmaf(z.x, sc, sh);
    float u1 = fmaf(z.y, sc, sh);
    float u2 = fmaf(z.z, sc, sh);
    float u3 = fmaf(z.w, sc, sh);
    float4 r;
    r.x = (u0 > 0.f ? u0 : expm1f(u0)) + xv.x;
    r.y = (u1 > 0.f ? u1 : expm1f(u1)) + xv.y;
    r.z = (u2 > 0.f ? u2 : expm1f(u2)) + xv.z;
    r.w = (u3 > 0.f ? u3 : expm1f(u3)) + xv.w;
    ((float4*)out)[i4] = r;
}

// ---------------- launch ----------------
extern "C" void kernel_launch(void* const* d_in, const int* in_sizes, int n_in,
                              void* d_out, int out_size) {
    const float* x     = (const float*)d_in[0];
    const float* C_re  = (const float*)d_in[1];
    const float* C_im  = (const float*)d_in[2];
    const float* lAr   = (const float*)d_in[3];
    const float* Aim   = (const float*)d_in[4];
    const float* ldt   = (const float*)d_in[5];
    const float* D     = (const float*)d_in[6];
    const float* W     = (const float*)d_in[7];
    const float* gamma = (const float*)d_in[8];
    const float* beta  = (const float*)d_in[9];
    float* out = (float*)d_out;

    k_setup<<<16, 256>>>(C_re, C_im, lAr, Aim, ldt);
    k_pass1<<<(Bx * Hx * NCx) / 8, 256>>>(x);
    k_carry<<<(Bx * Hx * Nx) / 256, 256>>>();
    k_pass2<<<Hx * NCx, 64>>>(x);
    k_act<<<(Bx * Hx * Lx) / (4 * 512), 512>>>(x, D);
    k_gemm<<<dim3(Lx / 64, 2, Bx), 256>>>(W);
    k_bnstat<<<dim3(Hx, 16), 256>>>();
    k_bnfin<<<1, Hx>>>(gamma, beta);
    k_final<<<(Bx * Hx * Lx) / (4 * 512), 512>>>(x, out);
}

// round 8
// speedup vs baseline: 1.0048x; 1.0048x over previous
#include <cuda_runtime.h>
#include <math.h>

#define Bx  8
#define Hx  128
#define Lx  8192
#define Nx  32
#define NCx 16
#define Tx  512
#define XSTR 516  // padded smem row stride for x staging (bank-spread)

// ---------------- device scratch (no allocations allowed) ----------------
__device__ float2 g_w [Hx*Nx];
__device__ float2 g_wT[Hx*Nx];
__device__ float2 g_K0[Hx*Nx];
__device__ float2 g_K1[Hx*Nx];

__device__ float2 g_U  [Bx*Hx*NCx*Nx];
__device__ float2 g_Lb [Bx*Hx*NCx*Nx];
__device__ float2 g_Sin[Bx*Hx*NCx*Nx];
__device__ float2 g_Rin[Bx*Hx*NCx*Nx];

__device__ float g_yf[Bx*Hx*Lx];
__device__ float g_yb[Bx*Hx*Lx];
__device__ float g_g [Bx*Hx*Lx];
__device__ float g_z [Bx*Hx*Lx];

__device__ float2 g_part[Hx*16];
__device__ float  g_scale[Hx];
__device__ float  g_shift[Hx];

// ---------------- setup: discretized SSM parameters ----------------
__global__ void k_setup(const float* __restrict__ C_re, const float* __restrict__ C_im,
                        const float* __restrict__ lAr,  const float* __restrict__ Aim,
                        const float* __restrict__ ldt) {
    int i = blockIdx.x * blockDim.x + threadIdx.x;
    if (i >= Hx * Nx) return;
    int h = i / Nx;
    float ar = expf(lAr[i]);
    float ai = Aim[i];
    float dt = expf(ldt[h]);
    // w = exp(dt*A), A = -ar + i*ai
    float mag = expf(-dt * ar);
    float sn, cs;
    sincosf(dt * ai, &sn, &cs);
    float wre = mag * cs, wim = mag * sn;
    g_w[i] = make_float2(wre, wim);
    // w^T in double (phase can be thousands of radians)
    double magT = exp(-(double)dt * (double)ar * (double)Tx);
    double phT  = (double)dt * (double)ai * (double)Tx;
    g_wT[i] = make_float2((float)(magT * cos(phT)), (float)(magT * sin(phT)));
    // F = (w-1)/A = (w-1)*conj(A)/|A|^2
    float den = ar * ar + ai * ai;
    float nre = (wre - 1.0f) * (-ar) + wim * ai;
    float nim = wim * (-ar) - (wre - 1.0f) * ai;
    float Fre = nre / den, Fim = nim / den;
    float c0r = C_re[i], c0i = C_im[i];
    g_K0[i] = make_float2(2.0f * (c0r * Fre - c0i * Fim), 2.0f * (c0r * Fim + c0i * Fre));
    float c1r = C_re[Hx * Nx + i], c1i = C_im[Hx * Nx + i];
    g_K1[i] = make_float2(2.0f * (c1r * Fre - c1i * Fim), 2.0f * (c1r * Fim + c1i * Fre));
}

// ---------------- pass 1: per-chunk local states (no outputs) ----------------
// warp w of each block handles chunk index widx = blockIdx.x*8 + w,
// widx = ((b*Hx+h)*NCx + c); lanes = 32 modes.
__global__ void k_pass1(const float* __restrict__ x) {
    __shared__ float xs[8 * Tx];
    int widx0 = blockIdx.x * 8;
    int base = widx0 * Tx;                 // contiguous (NCx*Tx == Lx, 8 | NCx)
    for (int i = threadIdx.x; i < 8 * Tx; i += blockDim.x) xs[i] = x[base + i];
    __syncthreads();

    int w = threadIdx.x >> 5, lane = threadIdx.x & 31;
    int widx = widx0 + w;
    int h = (widx / NCx) % Hx;
    float2 wv = g_w[h * Nx + lane];
    const float* xp = xs + w * Tx;

    float ur = 0.f, ui = 0.f;
#pragma unroll 8
    for (int t = 0; t < Tx; t++) {
        float xv = xp[t];
        float nr = fmaf(wv.x, ur, fmaf(-wv.y, ui, xv));
        float ni = fmaf(wv.x, ui, wv.y * ur);
        ur = nr; ui = ni;
    }
    g_U[widx * Nx + lane] = make_float2(ur, ui);

    float lr = 0.f, li = 0.f;
#pragma unroll 8
    for (int t = Tx - 1; t >= 0; t--) {
        float xv = xp[t];
        float nr = fmaf(wv.x, lr, fmaf(-wv.y, li, xv));
        float ni = fmaf(wv.x, li, wv.y * lr);
        lr = nr; li = ni;
    }
    g_Lb[widx * Nx + lane] = make_float2(lr, li);
}

// ---------------- combine carries across chunks ----------------
__global__ void k_carry() {
    int tau = blockIdx.x * blockDim.x + threadIdx.x;   // B*H*N = 32768 threads
    int bh = tau >> 5, n = tau & 31;
    int h = bh % Hx;
    float2 wT = g_wT[h * Nx + n];
    int base = bh * NCx * Nx + n;

    float sr = 0.f, si = 0.f;
    for (int c = 0; c < NCx; c++) {
        int idx = base + c * Nx;
        g_Sin[idx] = make_float2(sr, si);
        float2 u = g_U[idx];
        float nr = fmaf(wT.x, sr, fmaf(-wT.y, si, u.x));
        float ni = fmaf(wT.x, si, fmaf(wT.y, sr, u.y));
        sr = nr; si = ni;
    }
    float rr = 0.f, ri = 0.f;
    for (int c = NCx - 1; c >= 0; c--) {
        int idx = base + c * Nx;
        g_Rin[idx] = make_float2(rr, ri);
        float2 lb = g_Lb[idx];
        float nr = fmaf(wT.x, rr, fmaf(-wT.y, ri, lb.x));
        float ni = fmaf(wT.x, ri, fmaf(wT.y, rr, lb.y));
        rr = nr; ri = ni;
    }
}

// ---------------- pass 2: emit outputs ----------------
// block = (h, chunk c), 64 threads = 2 warps (fwd / bwd).
// lane = b*4 + q, q indexes an 8-mode group; 2 shuffles per step, 8 outputs per warp-step.
__global__ void k_pass2(const float* __restrict__ x) {
    __shared__ float xs[Bx * XSTR];
    int h = blockIdx.x / NCx, c = blockIdx.x % NCx;
    for (int i = threadIdx.x; i < Bx * Tx; i += blockDim.x) {
        int b = i >> 9, t = i & (Tx - 1);
        xs[b * XSTR + t] = x[((b * Hx + h) << 13) + (c << 9) + t];
    }
    __syncthreads();

    int warp = threadIdx.x >> 5;   // 0 = fwd, 1 = bwd
    int lane = threadIdx.x & 31;
    int b = lane >> 2, q = lane & 3;

    float wr[8], wi[8], kr[8], ki[8], sr[8], si[8];
    int pbase = h * Nx + q * 8;
    int sbase = ((b * Hx + h) * NCx + c) * Nx + q * 8;
#pragma unroll
    for (int m = 0; m < 8; m++) {
        float2 wv = g_w[pbase + m];  wr[m] = wv.x; wi[m] = wv.y;
        float2 kv = warp ? g_K1[pbase + m] : g_K0[pbase + m];
        kr[m] = kv.x; ki[m] = kv.y;
        float2 sv = warp ? g_Rin[sbase + m] : g_Sin[sbase + m];
        sr[m] = sv.x; si[m] = sv.y;
    }

    int obase = ((b * Hx + h) << 13) + (c << 9);
    const float* xp = xs + b * XSTR;

    if (warp == 0) {
#pragma unroll 2
        for (int t = 0; t < Tx; t++) {
            float xv = xp[t];
            float v = 0.f;
#pragma unroll
            for (int m = 0; m < 8; m++) {
                float nr = fmaf(wr[m], sr[m], fmaf(-wi[m], si[m], xv));
                float ni = fmaf(wr[m], si[m], wi[m] * sr[m]);
                sr[m] = nr; si[m] = ni;
                v = fmaf(kr[m], nr, fmaf(-ki[m], ni, v));
            }
            v += __shfl_xor_sync(0xffffffffu, v, 1);
            v += __shfl_xor_sync(0xffffffffu, v, 2);
            if (q == 0) g_yf[obase + t] = v;
        }
    } else {
#pragma unroll 2
        for (int t = Tx - 1; t >= 0; t--) {
            float xv = xp[t];
            float v = 0.f;
#pragma unroll
            for (int m = 0; m < 8; m++)
                v = fmaf(kr[m], sr[m], fmaf(-ki[m], si[m], v));
            v += __shfl_xor_sync(0xffffffffu, v, 1);
            v += __shfl_xor_sync(0xffffffffu, v, 2);
            if (q == 0) g_yb[obase + t] = v;
#pragma unroll
            for (int m = 0; m < 8; m++) {
                float nr = fmaf(wr[m], sr[m], fmaf(-wi[m], si[m], xv));
                float ni = fmaf(wr[m], si[m], wi[m] * sr[m]);
                sr[m] = nr; si[m] = ni;
            }
        }
    }
}

// ---------------- g = gelu(yf + yb + D*x) ----------------
__global__ void k_act(const float* __restrict__ x, const float* __restrict__ D) {
    int i4 = blockIdx.x * blockDim.x + threadIdx.x;     // 2,097,152 float4s
    int flat = i4 << 2;
    int ch = (flat >> 13) & (Hx - 1);
    float dv = __ldg(&D[ch]);
    float4 f  = ((const float4*)g_yf)[i4];
    float4 bb = ((const float4*)g_yb)[i4];
    float4 xv = ((const float4*)x)[i4];
    float u0 = f.x + bb.x + dv * xv.x;
    float u1 = f.y + bb.y + dv * xv.y;
    float u2 = f.z + bb.z + dv * xv.z;
    float u3 = f.w + bb.w + dv * xv.w;
    const float is2 = 0.70710678118654752f;
    float4 r;
    r.x = 0.5f * u0 * (1.0f + erff(u0 * is2));
    r.y = 0.5f * u1 * (1.0f + erff(u1 * is2));
    r.z = 0.5f * u2 * (1.0f + erff(u2 * is2));
    r.w = 0.5f * u3 * (1.0f + erff(u3 * is2));
    ((float4*)g_g)[i4] = r;
}

// ---------------- pointwise conv: z[b,o,l] = sum_h W[o,h]*g[b,h,l] ----------------
__global__ void k_gemm(const float* __restrict__ W) {
    __shared__ float Ws[64][68];
    __shared__ float gs[64][68];
    int l0 = blockIdx.x * 64;
    int o0 = blockIdx.y * 64;
    int b  = blockIdx.z;
    int tx = threadIdx.x & 15, ty = threadIdx.x >> 4;
    float acc[4][4] = {};

    for (int hc = 0; hc < Hx; hc += 64) {
        __syncthreads();
        for (int r = threadIdx.x; r < 4096; r += 256) {
            int oo = r >> 6, hh = r & 63;
            Ws[hh][oo] = W[(o0 + oo) * Hx + hc + hh];
        }
        for (int r = threadIdx.x; r < 4096; r += 256) {
            int hh = r >> 6, ll = r & 63;
            gs[hh][ll] = g_g[((b * Hx + hc + hh) << 13) + l0 + ll];
        }
        __syncthreads();
#pragma unroll 8
        for (int hh = 0; hh < 64; hh++) {
            float4 wv = *(const float4*)&Ws[hh][ty * 4];
            float4 gv = *(const float4*)&gs[hh][tx * 4];
            float wa[4] = {wv.x, wv.y, wv.z, wv.w};
            float ga[4] = {gv.x, gv.y, gv.z, gv.w};
#pragma unroll
            for (int i = 0; i < 4; i++)
#pragma unroll
                for (int j = 0; j < 4; j++)
                    acc[i][j] = fmaf(wa[i], ga[j], acc[i][j]);
        }
    }
#pragma unroll
    for (int i = 0; i < 4; i++) {
        int row = ((b * Hx + o0 + ty * 4 + i) << 13) + l0 + tx * 4;
        *(float4*)&g_z[row] = make_float4(acc[i][0], acc[i][1], acc[i][2], acc[i][3]);
    }
}

// ---------------- BN statistics (deterministic two-level reduction) ----------------
__global__ void k_bnstat() {
    int ch = blockIdx.x, seg = blockIdx.y;
    float s = 0.f, s2 = 0.f;
    for (int j = 0; j < 16; j++) {
        int f = seg * 4096 + j * 256 + threadIdx.x;
        int b = f >> 13, l = f & (Lx - 1);
        float v = g_z[((b * Hx + ch) << 13) + l];
        s += v;
        s2 = fmaf(v, v, s2);
    }
    __shared__ float rs[256], rq[256];
    rs[threadIdx.x] = s; rq[threadIdx.x] = s2;
    __syncthreads();
    for (int st = 128; st > 0; st >>= 1) {
        if (threadIdx.x < st) {
            rs[threadIdx.x] += rs[threadIdx.x + st];
            rq[threadIdx.x] += rq[threadIdx.x + st];
        }
        __syncthreads();
    }
    if (threadIdx.x == 0) g_part[ch * 16 + seg] = make_float2(rs[0], rq[0]);
}

__global__ void k_bnfin(const float* __restrict__ gamma, const float* __restrict__ beta) {
    int ch = threadIdx.x;
    double s = 0.0, s2 = 0.0;
    for (int j = 0; j < 16; j++) {
        float2 p = g_part[ch * 16 + j];
        s += p.x; s2 += p.y;
    }
    double cnt = (double)Bx * (double)Lx;
    double mean = s / cnt;
    double var = s2 / cnt - mean * mean;
    float scale = (float)((double)gamma[ch] / sqrt(var + 1e-5));
    g_scale[ch] = scale;
    g_shift[ch] = beta[ch] - (float)mean * scale;
}

// ---------------- out = elu(bn(z)) + x ----------------
__global__ void k_final(const float* __restrict__ x, float* __restrict__ out) {
    int i4 = blockIdx.x * blockDim.x + threadIdx.x;
    int flat = i4 << 2;
    int ch = (flat >> 13) & (Hx - 1);
    float sc = __ldg(&g_scale[ch]);
    float sh = __ldg(&g_shift[ch]);
    float4 z  = ((const float4*)g_z)[i4];
    float4 xv = ((const float4*)x)[i4];
    float u0 = fmaf(z.x, sc, sh);
    float u1 = fmaf(z.y, sc, sh);
    float u2 = fmaf(z.z, sc, sh);
    float u3 = fmaf(z.w, sc, sh);
    float4 r;
    r.x = (u0 > 0.f ? u0 : expm1f(u0)) + xv.x;
    r.y = (u1 > 0.f ? u1 : expm1f(u1)) + xv.y;
    r.z = (u2 > 0.f ? u2 : expm1f(u2)) + xv.z;
    r.w = (u3 > 0.f ? u3 : expm1f(u3)) + xv.w;
    ((float4*)out)[i4] = r;
}

// ---------------- launch ----------------
extern "C" void kernel_launch(void* const* d_in, const int* in_sizes, int n_in,
                              void* d_out, int out_size) {
    const float* x     = (const float*)d_in[0];
    const float* C_re  = (const float*)d_in[1];
    const float* C_im  = (const float*)d_in[2];
    const float* lAr   = (const float*)d_in[3];
    const float* Aim   = (const float*)d_in[4];
    const float* ldt   = (const float*)d_in[5];
    const float* D     = (const float*)d_in[6];
    const float* W     = (const float*)d_in[7];
    const float* gamma = (const float*)d_in[8];
    const float* beta  = (const float*)d_in[9];
    float* out = (float*)d_out;

    k_setup<<<16, 256>>>(C_re, C_im, lAr, Aim, ldt);
    k_pass1<<<(Bx * Hx * NCx) / 8, 256>>>(x);
    k_carry<<<(Bx * Hx * Nx) / 256, 256>>>();
    k_pass2<<<Hx * NCx, 64>>>(x);
    k_act<<<(Bx * Hx * Lx) / (4 * 512), 512>>>(x, D);
    k_gemm<<<dim3(Lx / 64, 2, Bx), 256>>>(W);
    k_bnstat<<<dim3(Hx, 16), 256>>>();
    k_bnfin<<<1, Hx>>>(gamma, beta);
    k_final<<<(Bx * Hx * Lx) / (4 * 512), 512>>>(x, out);
}